// round 1
// baseline (speedup 1.0000x reference)
#include <cuda_runtime.h>

// Problem constants
#define B   32
#define DE  256
#define T   32
#define C   128
#define HW  16384   // 128*128

// Scratch for the projected embeddings e_ : [B][C][T]
__device__ float g_e[B * C * T];

// Packed dual-FP32 FMA (sm_103a): d = a*b + c componentwise.
__device__ __forceinline__ float2 ffma2(float2 a, float2 b, float2 c) {
    unsigned long long ua = *reinterpret_cast<unsigned long long*>(&a);
    unsigned long long ub = *reinterpret_cast<unsigned long long*>(&b);
    unsigned long long uc = *reinterpret_cast<unsigned long long*>(&c);
    unsigned long long ud;
    asm("fma.rn.f32x2 %0, %1, %2, %3;" : "=l"(ud) : "l"(ua), "l"(ub), "l"(uc));
    return *reinterpret_cast<float2*>(&ud);
}

// ---------------------------------------------------------------------------
// Kernel 1: e_[b][c][t] = sum_d e[b][d][t] * Wd[d][c] + bias[c]
// grid (2, 32), block 256. Each thread: one c, 8 t's.
// ---------------------------------------------------------------------------
__global__ void proj_kernel(const float* __restrict__ e,
                            const float* __restrict__ Wd,
                            const float* __restrict__ bias) {
    __shared__ float e_sm[DE * T];  // 32 KB, [d][t]
    const int b = blockIdx.y;

    const float4* e4  = reinterpret_cast<const float4*>(e + b * DE * T);
    float4*       es4 = reinterpret_cast<float4*>(e_sm);
    for (int i = threadIdx.x; i < DE * T / 4; i += blockDim.x) es4[i] = e4[i];
    __syncthreads();

    const int c  = blockIdx.x * 64 + (threadIdx.x >> 2);
    const int t0 = (threadIdx.x & 3) * 8;

    float acc[8];
#pragma unroll
    for (int i = 0; i < 8; i++) acc[i] = 0.0f;

#pragma unroll 4
    for (int d = 0; d < DE; d++) {
        const float w = __ldg(&Wd[d * C + c]);
        const float4* er = reinterpret_cast<const float4*>(e_sm + d * T + t0);
        const float4 v0 = er[0];
        const float4 v1 = er[1];
        acc[0] = fmaf(w, v0.x, acc[0]);
        acc[1] = fmaf(w, v0.y, acc[1]);
        acc[2] = fmaf(w, v0.z, acc[2]);
        acc[3] = fmaf(w, v0.w, acc[3]);
        acc[4] = fmaf(w, v1.x, acc[4]);
        acc[5] = fmaf(w, v1.y, acc[5]);
        acc[6] = fmaf(w, v1.z, acc[6]);
        acc[7] = fmaf(w, v1.w, acc[7]);
    }

    const float bc = bias[c];
    float* outp = g_e + (b * C + c) * T + t0;
#pragma unroll
    for (int i = 0; i < 8; i++) outp[i] = acc[i] + bc;
}

// ---------------------------------------------------------------------------
// Kernel 2: fused scores + softmax + context + concat.
// grid (HW/256, B), block 128 (4 warps). Each warp owns 64 pixels; each lane
// owns 2 adjacent pixels. s/beta live t-packed as float2 in registers, so the
// softmax over T=32 is fully lane-local.
// ---------------------------------------------------------------------------

// Accumulate one channel into the t-packed score accumulators (both pixels).
#define SCHAN(vA, vB, ch) do {                                                 \
    const float2 h2a = make_float2((vA), (vA));                                \
    const float2 h2b = make_float2((vB), (vB));                                \
    const float4* er_ = reinterpret_cast<const float4*>(e_sm + (ch) * T);      \
    _Pragma("unroll")                                                          \
    for (int j4 = 0; j4 < 8; j4++) {                                           \
        const float4 ev = er_[j4];                                             \
        const float2 e0 = make_float2(ev.x, ev.y);                             \
        const float2 e1 = make_float2(ev.z, ev.w);                             \
        sA[2 * j4]     = ffma2(h2a, e0, sA[2 * j4]);                           \
        sA[2 * j4 + 1] = ffma2(h2a, e1, sA[2 * j4 + 1]);                       \
        sB[2 * j4]     = ffma2(h2b, e0, sB[2 * j4]);                           \
        sB[2 * j4 + 1] = ffma2(h2b, e1, sB[2 * j4 + 1]);                       \
    }                                                                          \
} while (0)

__global__ __launch_bounds__(128, 3)
void attn_kernel(const float* __restrict__ h, float* __restrict__ out) {
    __shared__ float e_sm[C * T];  // 16 KB, [c][t]

    const int b     = blockIdx.y;
    const int pbase = blockIdx.x * 256;
    const int tid   = threadIdx.x;

    // Stage e_ for this batch (broadcast-read later).
    {
        const float4* ge4 = reinterpret_cast<const float4*>(g_e + b * C * T);
        float4*       es4 = reinterpret_cast<float4*>(e_sm);
        for (int i = tid; i < C * T / 4; i += 128) es4[i] = ge4[i];
    }

    // Coalesced copy of h into the output's second half (also warms L2).
    {
        const float4* h4 = reinterpret_cast<const float4*>(h + (b * HW + pbase) * C);
        float4*       o4 = reinterpret_cast<float4*>(out + (b * HW + pbase) * 2 * C);
        for (int i = tid; i < 256 * C / 4; i += 128) {
            const int p  = i >> 5;   // 32 float4 per pixel row
            const int c4 = i & 31;
            o4[p * 64 + 32 + c4] = h4[i];
        }
    }
    __syncthreads();

    const int warp = tid >> 5;
    const int lane = tid & 31;
    const int p0   = pbase + warp * 64 + lane * 2;  // this lane's pixels: p0, p0+1

    const float4* hp0 = reinterpret_cast<const float4*>(h + (b * HW + p0) * C);
    const float4* hp1 = hp0 + 32;  // next pixel row (+128 floats)

    // ---- Phase 1: scores s[t] for both pixels (t-packed float2 x16) ----
    float2 sA[16], sB[16];
#pragma unroll
    for (int j = 0; j < 16; j++) {
        sA[j] = make_float2(0.0f, 0.0f);
        sB[j] = make_float2(0.0f, 0.0f);
    }

#pragma unroll 4
    for (int cc = 0; cc < 32; cc++) {  // 32 chunks of 4 channels
        const float4 ha = hp0[cc];
        const float4 hb = hp1[cc];
        const int ch = cc * 4;
        SCHAN(ha.x, hb.x, ch + 0);
        SCHAN(ha.y, hb.y, ch + 1);
        SCHAN(ha.z, hb.z, ch + 2);
        SCHAN(ha.w, hb.w, ch + 3);
    }

    // ---- Phase 2: lane-local softmax over T (unnormalized; fold 1/sum later)
    float2 m2a = sA[0], m2b = sB[0];
#pragma unroll
    for (int j = 1; j < 16; j++) {
        m2a.x = fmaxf(m2a.x, sA[j].x); m2a.y = fmaxf(m2a.y, sA[j].y);
        m2b.x = fmaxf(m2b.x, sB[j].x); m2b.y = fmaxf(m2b.y, sB[j].y);
    }
    const float mA = fmaxf(m2a.x, m2a.y);
    const float mB = fmaxf(m2b.x, m2b.y);

    float2 suma = make_float2(0.0f, 0.0f), sumb = make_float2(0.0f, 0.0f);
#pragma unroll
    for (int j = 0; j < 16; j++) {
        sA[j].x = __expf(sA[j].x - mA); sA[j].y = __expf(sA[j].y - mA);
        sB[j].x = __expf(sB[j].x - mB); sB[j].y = __expf(sB[j].y - mB);
        suma.x += sA[j].x; suma.y += sA[j].y;
        sumb.x += sB[j].x; sumb.y += sB[j].y;
    }
    const float invA = 1.0f / (suma.x + suma.y);
    const float invB = 1.0f / (sumb.x + sumb.y);

    // ---- Phase 3: context c[ch] = sum_t e_[ch][t] * beta[t], both pixels ----
    float4* op0 = reinterpret_cast<float4*>(out + (b * HW + p0) * 2 * C);
    float4* op1 = op0 + 64;  // next pixel's output row

#pragma unroll 2
    for (int g = 0; g < 32; g++) {  // 4 output channels per group -> float4 store
        float4 r0, r1;
        float* r0p = reinterpret_cast<float*>(&r0);
        float* r1p = reinterpret_cast<float*>(&r1);
#pragma unroll
        for (int k = 0; k < 4; k++) {
            const int ch = g * 4 + k;
            const float4* er = reinterpret_cast<const float4*>(e_sm + ch * T);
            float2 a0 = make_float2(0.0f, 0.0f);
            float2 a1 = make_float2(0.0f, 0.0f);
#pragma unroll
            for (int j4 = 0; j4 < 8; j4++) {
                const float4 ev = er[j4];
                const float2 e0 = make_float2(ev.x, ev.y);
                const float2 e1 = make_float2(ev.z, ev.w);
                a0 = ffma2(e0, sA[2 * j4], a0);
                a0 = ffma2(e1, sA[2 * j4 + 1], a0);
                a1 = ffma2(e0, sB[2 * j4], a1);
                a1 = ffma2(e1, sB[2 * j4 + 1], a1);
            }
            r0p[k] = (a0.x + a0.y) * invA;
            r1p[k] = (a1.x + a1.y) * invB;
        }
        op0[g] = r0;
        op1[g] = r1;
    }
}

// ---------------------------------------------------------------------------
extern "C" void kernel_launch(void* const* d_in, const int* in_sizes, int n_in,
                              void* d_out, int out_size) {
    const float* e    = (const float*)d_in[0];  // [B, DE, T]
    const float* h    = (const float*)d_in[1];  // [B, H, W, C]
    const float* Wd   = (const float*)d_in[2];  // [DE, C]
    const float* bias = (const float*)d_in[3];  // [C]
    float* out = (float*)d_out;                 // [B, H, W, 2C]

    proj_kernel<<<dim3(2, B), 256>>>(e, Wd, bias);
    attn_kernel<<<dim3(HW / 256, B), 128>>>(h, out);
}